// round 16
// baseline (speedup 1.0000x reference)
#include <cuda_runtime.h>
#include <stdint.h>

#define N_MAX     20000
#define DEG       32
#define NBLOCKS   112
#define NTHREADS  512
#define NWB       (NTHREADS / 32)      // 16 warps per block
#define CHUNK_CAP 192                  // >= ceil(N_MAX/NBLOCKS)=179, >= FAST_MAX
#define FAST_MAX  128                  // small-level single-block fast path
#define MAX_ITERS 12                   // ceil(CHUNK_CAP / NWB)
#define MAX_LEV   60

// Scratch (static __device__ — no allocations allowed)
__device__ unsigned g_packed[N_MAX * DEG];   // (v<<5)|rank per edge (orig layout)
__device__ float4   g_nq[N_MAX];             // node quaternions
__device__ unsigned g_claim[N_MAX];          // min claim key (reinit per run)
__device__ unsigned g_queue[N_MAX];          // tagged queue: (lev+1)<<16 | v
__device__ unsigned long long g_cnt[MAX_LEV + 2][NBLOCKS];  // per-level counts
__device__ unsigned long long g_ctrl;        // fast->big / DONE control word

// single-use hierarchical grid barrier (monotone counters; replay-safe)
__device__ unsigned          g_bar_sub[4];
__device__ unsigned          g_bar_root;
__device__ volatile unsigned g_bar_gen;

__device__ __forceinline__ void grid_barrier() {
    __syncthreads();
    if (threadIdx.x == 0) {
        unsigned gen = g_bar_gen;
        __threadfence();
        int s = blockIdx.x & 3;
        unsigned my = atomicAdd(&g_bar_sub[s], 1u) + 1u;
        if ((my % (NBLOCKS / 4)) == 0u) {
            unsigned r = atomicAdd(&g_bar_root, 1u) + 1u;
            if ((r & 3u) == 0u) { __threadfence(); g_bar_gen = gen + 1u; }
        }
        while (g_bar_gen == gen) __nanosleep(20);
        __threadfence();
    }
    __syncthreads();
}

// release/acquire helpers (gpu scope)
__device__ __forceinline__ unsigned ld_acq32(const unsigned* p) {
    unsigned v;
    asm volatile("ld.global.acquire.gpu.b32 %0, [%1];" : "=r"(v) : "l"(p) : "memory");
    return v;
}
__device__ __forceinline__ void st_rel32(unsigned* p, unsigned v) {
    asm volatile("st.global.release.gpu.b32 [%0], %1;" :: "l"(p), "r"(v) : "memory");
}
__device__ __forceinline__ unsigned long long ld_acq64(const unsigned long long* p) {
    unsigned long long v;
    asm volatile("ld.global.acquire.gpu.b64 %0, [%1];" : "=l"(v) : "l"(p) : "memory");
    return v;
}
__device__ __forceinline__ void st_rel64(unsigned long long* p, unsigned long long v) {
    asm volatile("st.global.release.gpu.b64 [%0], %1;" :: "l"(p), "l"(v) : "memory");
}

// Replicate XLA's acos lowering: acos(x)=2*atan2(sqrt(1-x*x),1+x), all f32 RN.
__device__ __forceinline__ float err_key(float w) {
    float x = fminf(fabsf(w), 1.0f);
    float t = __fsub_rn(1.0f, __fmul_rn(x, x));
    float s = __fsqrt_rn(t);
    float a = atan2f(s, __fadd_rn(1.0f, x));
    float acosv = __fmul_rn(2.0f, a);
    float deg   = __fmul_rn(acosv, 57.29577951308232f);
    return __fmul_rn(2.0f, deg);
}

struct Smem {
    int      s_u[CHUNK_CAP];
    unsigned s_winl[CHUNK_CAP];
    unsigned s_winr[CHUNK_CAP];
    int      s_off[CHUNK_CAP];
    unsigned s_wlist[CHUNK_CAP * 32];   // rank-ordered winner records (ei<<5)|lane
    int      s_wsum[NWB];
    int      s_woff[NWB];
    int      s_total, s_before, s_gtot, s_start;
    unsigned long long s_ctrl;
};

// Process one BFS level. Claims for this level's frontier were ALREADY issued
// by the previous level's Phase C (claim forwarding), so the level is:
//   acquire-spin queue entries (gives claim visibility) -> winner check ->
//   scan -> [count gather if big] -> Phase C: per-winner claims for the NEXT
//   level + quat + release-tagged queue write.
// Exact reference order: node v claimed by min key (queue_pos<<5 | rank);
// next-level queue = ascending winner key.
__device__ __forceinline__ int process_level(
    Smem& sm, const float4* __restrict__ ea4, float* __restrict__ out, int base,
    int lev, int beg, int end, int start, bool big)
{
    const int tid = threadIdx.x, lane = tid & 31, wid = tid >> 5, bid = blockIdx.x;
    const unsigned FULL = 0xffffffffu;
    const int len = end - beg;
    int cbeg, clen;
    if (big) {
        int chunk = (len + NBLOCKS - 1) / NBLOCKS;         // <= CHUNK_CAP
        cbeg = beg + bid * chunk;
        int cend = cbeg + chunk; if (cend > end) cend = end;
        clen = cend - cbeg; if (clen < 0) clen = 0;
    } else { cbeg = beg; clen = len; }
    const unsigned tag = (unsigned)(lev + 1);

    if (clen > 0) {
        // batched acquire-spin over ALL level entries (claims visibility needs
        // every producer's release); independent loads per pass => pipelined
        unsigned long long pend = 0ULL;
        for (int i = tid, k = 0; i < len; i += NTHREADS, k++)
            pend |= 1ULL << k;
        while (pend) {
            for (int i = tid, k = 0; i < len; i += NTHREADS, k++) {
                if (!((pend >> k) & 1ULL)) continue;
                unsigned qv = ld_acq32(&g_queue[beg + i]);
                if ((qv >> 16) == tag) {
                    pend &= ~(1ULL << k);
                    int rel = (beg + i) - cbeg;
                    if (rel >= 0 && rel < clen)
                        sm.s_u[rel] = (int)(qv & 0xffffu);
                }
            }
            if (pend) __nanosleep(20);
        }
    }
    __syncthreads();

    // winner check: pipelined pk + claim loads, then ballots
    unsigned pk_arr[MAX_ITERS];
    #pragma unroll
    for (int it = 0; it < MAX_ITERS; it++) {
        int ei = wid + it * NWB;
        if (ei < clen) pk_arr[it] = g_packed[(sm.s_u[ei] << 5) + lane];
    }
    unsigned cl_arr[MAX_ITERS];
    #pragma unroll
    for (int it = 0; it < MAX_ITERS; it++) {
        int ei = wid + it * NWB;
        if (ei < clen) cl_arr[it] = __ldcg(&g_claim[pk_arr[it] >> 5]);
    }
    #pragma unroll
    for (int it = 0; it < MAX_ITERS; it++) {
        int ei = wid + it * NWB;
        if (ei < clen) {
            int v = (int)(pk_arr[it] >> 5); unsigned rk = pk_arr[it] & 31u;
            bool win = (v != start) &&
                       (cl_arr[it] == ((((unsigned)(cbeg + ei)) << 5) | rk));
            unsigned lm = __ballot_sync(FULL, win);
            unsigned rm = win ? (1u << rk) : 0u;
            #pragma unroll
            for (int d = 16; d; d >>= 1) rm |= __shfl_xor_sync(FULL, rm, d);
            if (lane == 0) { sm.s_winl[ei] = lm; sm.s_winr[ei] = rm; }
        }
    }
    __syncthreads();

    // exclusive scan of winner counts over the chunk
    int c = (tid < clen) ? __popc(sm.s_winl[tid]) : 0;
    int x = c;
    #pragma unroll
    for (int d = 1; d < 32; d <<= 1) {
        int y = __shfl_up_sync(FULL, x, d);
        if (lane >= d) x += y;
    }
    if (lane == 31) sm.s_wsum[wid] = x;
    __syncthreads();
    if (wid == 0 && lane < NWB) {
        int w = sm.s_wsum[lane], xx = w;
        #pragma unroll
        for (int d = 1; d < NWB; d <<= 1) {
            int y = __shfl_up_sync(0x0000ffffu, xx, d);
            if (lane >= d) xx += y;
        }
        sm.s_woff[lane] = xx - w;
        if (lane == NWB - 1) sm.s_total = xx;
    }
    __syncthreads();
    if (tid < clen) sm.s_off[tid] = x - c + sm.s_woff[wid];
    __syncthreads();

    // winner list (rank-ordered within entry => pos = blkoff + list index)
    #pragma unroll
    for (int it = 0; it < MAX_ITERS; it++) {
        int ei = wid + it * NWB;
        if (ei < clen) {
            unsigned lm = sm.s_winl[ei];
            if ((lm >> lane) & 1u) {
                unsigned rk = pk_arr[it] & 31u;
                unsigned rm = sm.s_winr[ei];
                int idx = sm.s_off[ei] + __popc(rm & ((1u << rk) - 1u));
                sm.s_wlist[idx] = (((unsigned)ei) << 5) | (unsigned)lane;
            }
        }
    }

    int blkoff, gtot;
    if (big) {
        if (tid == 0)
            st_rel64(&g_cnt[lev][bid],
                     (((unsigned long long)tag) << 32) | (unsigned)sm.s_total);
        if (wid == 0) {
            int accb = 0, acct = 0;
            for (int j = lane; j < NBLOCKS; j += 32) {
                unsigned long long vv;
                for (;;) {
                    vv = ld_acq64(&g_cnt[lev][j]);
                    if ((unsigned)(vv >> 32) == tag) break;
                    __nanosleep(20);
                }
                int cc = (int)(vv & 0xffffffffu);
                acct += cc; if (j < bid) accb += cc;
            }
            #pragma unroll
            for (int d = 16; d; d >>= 1) {
                accb += __shfl_xor_sync(FULL, accb, d);
                acct += __shfl_xor_sync(FULL, acct, d);
            }
            if (lane == 0) { sm.s_before = accb; sm.s_gtot = acct; }
        }
        __syncthreads();
        blkoff = end + sm.s_before;
        gtot   = sm.s_gtot;
    } else {
        __syncthreads();            // publish s_wlist
        blkoff = end;
        gtot   = sm.s_total;
    }

    // Phase C: warp per winner — forward-claim v's edges for the next level,
    // compute quat, release-publish the tagged queue entry.
    for (int wi = wid; wi < sm.s_total; wi += NWB) {
        unsigned rec = sm.s_wlist[wi];
        int ei = (int)(rec >> 5), wl = (int)(rec & 31u);
        int u  = sm.s_u[ei];
        unsigned pkw = g_packed[(u << 5) + wl];        // uniform, L1 hit
        int v = (int)(pkw >> 5);
        int pos = blkoff + wi;
        // forward claims: all 32 edges of v with key (pos<<5)|rank
        unsigned pk2 = g_packed[(v << 5) + lane];
        atomicMin(&g_claim[pk2 >> 5],
                  (((unsigned)pos) << 5) | (pk2 & 31u));
        if (lane == 0) {
            int e = (u << 5) + wl;
            float4 q  = ea4[e];
            float4 uq = __ldcg(&g_nq[u]);
            // qmul(inv(q), qu):  inv(q) = (w, -x, -y, -z)
            float w1 = q.x, x1 = -q.y, y1 = -q.z, z1 = -q.w;
            float4 r;
            r.x = w1*uq.x - x1*uq.y - y1*uq.z - z1*uq.w;
            r.y = w1*uq.y + x1*uq.x + y1*uq.w - z1*uq.z;
            r.z = w1*uq.z - x1*uq.w + y1*uq.x + z1*uq.y;
            r.w = w1*uq.w + x1*uq.z - y1*uq.y + z1*uq.x;
            __stcg(&g_nq[v], r);
            __stcg(&out[base + 4*v + 0], r.x);
            __stcg(&out[base + 4*v + 1], r.y);
            __stcg(&out[base + 4*v + 2], r.z);
            __stcg(&out[base + 4*v + 3], r.w);
        }
        __syncwarp();   // claims + quat happen-before the release publish
        if (lane == 0)
            st_rel32(&g_queue[pos], ((tag + 1u) << 16) | (unsigned)v);
    }
    __syncthreads();   // s_* reuse safety for next level
    return gtot;
}

__global__ __launch_bounds__(NTHREADS, 1)
void spt_kernel(const float* __restrict__ edge_attr,
                const int*   __restrict__ edge_index,
                const int*   __restrict__ start_ptr,
                float* __restrict__ out, int N, int E, int base) {
    __shared__ Smem sm;
    const int tid = threadIdx.x, lane = tid & 31, wid = tid >> 5, bid = blockIdx.x;
    const unsigned FULL = 0xffffffffu;

    if (tid == 0) {
        int s = start_ptr ? __ldcg(start_ptr) : 0;
        if (s < 0 || s >= N) s = 0;
        sm.s_start = s;
    }
    __syncthreads();
    const int start = sm.s_start;

    // ---- per-run resets (pre-barrier) ----
    if (tid == 0 && bid == 0) {
        g_ctrl = 0ULL;
        g_nq[start] = make_float4(1.f, 0.f, 0.f, 0.f);
        for (int i = 0; i < base; i++) out[i] = (float)start;
    }
    for (int l = tid; l < MAX_LEV + 2; l += NTHREADS) g_cnt[l][bid] = 0ULL;

    for (int i = bid * NTHREADS + tid; i < N; i += NBLOCKS * NTHREADS) {
        g_claim[i] = 0xffffffffu;
        g_queue[i] = 0u;
        out[base + 4*i + 0] = 1.f;
        out[base + 4*i + 1] = 0.f;
        out[base + 4*i + 2] = 0.f;
        out[base + 4*i + 3] = 0.f;
    }

    // ---- rank phase: stable rank of each edge within its node ----
    bool     own_start = false;       // this warp ranked the start node
    unsigned start_pk  = 0;
    for (int node = bid * NWB + wid; node < N; node += NBLOCKS * NWB) {
        int e = (node << 5) + lane;
        int v = edge_index[E + e];             // dst row of edge_index [2,E]
        float err = err_key(edge_attr[4 * e]); // component 0 = w
        unsigned kb = __float_as_uint(err);    // err>=0: bits order-preserving
        int rk = 0;
        #pragma unroll
        for (int j = 0; j < 32; j++) {
            unsigned kj = __shfl_sync(FULL, kb, j);
            rk += (kj < kb) || (kj == kb && j < lane);
        }
        unsigned pk = (((unsigned)v) << 5) | (unsigned)rk;
        g_packed[e] = pk;
        if (node == start) { own_start = true; start_pk = pk; }
    }

    grid_barrier();

    // start node: forward-claim its edges (key = (0<<5)|rank), then publish
    // the level-0 queue entry with release so consumers see the claims.
    if (own_start) {
        atomicMin(&g_claim[start_pk >> 5], start_pk & 31u);
        __syncwarp();
        if (lane == 0)
            st_rel32(&g_queue[0], (1u << 16) | (unsigned)start);
    }

    // ---- level-synchronous BFS (R7 sync topology) ----
    const float4* ea4 = reinterpret_cast<const float4*>(edge_attr);
    int lev = 0, beg = 0, end = 1;
    unsigned long long last_ctrl = 0ULL;
    bool prev_big = false;

    while (true) {
        int len = end - beg;
        if (len <= 0 || lev >= MAX_LEV) {
            if (bid == 0 && tid == 0)
                st_rel64(&g_ctrl, (1ULL << 63) |
                                  (((unsigned long long)(lev + 1)) << 32));
            return;
        }
        bool fast = (len <= FAST_MAX);
        if (fast && bid != 0) {
            // sleep until block 0 publishes the next big level (or DONE)
            if (tid == 0) {
                unsigned long long cw;
                for (;;) {
                    cw = ld_acq64(&g_ctrl);
                    if (cw != last_ctrl) break;
                    __nanosleep(60);
                }
                sm.s_ctrl = cw;
            }
            __syncthreads();
            unsigned long long cw = sm.s_ctrl;
            last_ctrl = cw;
            if (cw >> 63) return;
            lev = (int)((cw >> 32) & 0xffffu) - 1;
            beg = (int)((cw >> 16) & 0xffffu);
            end = (int)(cw & 0xffffu);
            int gtot = process_level(sm, ea4, out, base, lev, beg, end, start, true);
            prev_big = true;
            beg = end; end += gtot; lev++;
            continue;
        }
        if (!fast && !prev_big && bid == 0 && tid == 0)
            st_rel64(&g_ctrl, (((unsigned long long)(lev + 1)) << 32) |
                              (((unsigned long long)beg) << 16) | (unsigned)end);
        int gtot = process_level(sm, ea4, out, base, lev, beg, end, start, !fast);
        prev_big = !fast;
        beg = end; end += gtot; lev++;
    }
}

extern "C" void kernel_launch(void* const* d_in, const int* in_sizes, int n_in,
                              void* d_out, int out_size) {
    const float* edge_attr  = (const float*)d_in[0];
    const int*   edge_index = (const int*)d_in[1];
    const int*   start_ptr  = (n_in >= 3) ? (const int*)d_in[2] : nullptr;
    float* out = (float*)d_out;

    int E = in_sizes[0] / 4;     // edge_attr is [E,4]
    int N = E / DEG;
    if (N > N_MAX) N = N_MAX;
    int base = out_size - N * 4;
    if (base < 0) base = 0;

    spt_kernel<<<NBLOCKS, NTHREADS>>>(edge_attr, edge_index, start_ptr, out, N, E, base);
}

// round 17
// speedup vs baseline: 3.0194x; 3.0194x over previous
#include <cuda_runtime.h>
#include <stdint.h>

#define N_MAX     20000
#define DEG       32
#define NBLOCKS   112
#define NTHREADS  512
#define NWB       (NTHREADS / 32)      // 16 warps per block
#define CHUNK_CAP 192                  // >= ceil(N_MAX/NBLOCKS)=179, >= FAST_MAX
#define FAST_MAX  128                  // small-level single-block fast path
#define MAX_ITERS 12                   // ceil(CHUNK_CAP / NWB)
#define MAX_LEV   60

// Scratch (static __device__ — no allocations allowed)
__device__ unsigned g_packed[N_MAX * DEG];   // (v<<5)|rank per edge (orig layout)
__device__ float4   g_nq[N_MAX];             // node quaternions
__device__ unsigned g_claim[N_MAX];          // min claim key (reinit per run)
__device__ unsigned g_queue[N_MAX];          // tagged queue: (lev+1)<<16 | v
__device__ unsigned g_slotA[NBLOCKS];        // per-block claim-done tag (monotone)
__device__ unsigned long long g_cnt[MAX_LEV + 2][NBLOCKS];  // per-level counts
__device__ unsigned long long g_ctrl;        // fast->big / DONE control word

// single-use hierarchical grid barrier (monotone counters; replay-safe)
__device__ unsigned          g_bar_sub[4];
__device__ unsigned          g_bar_root;
__device__ volatile unsigned g_bar_gen;

__device__ __forceinline__ void grid_barrier() {
    __syncthreads();
    if (threadIdx.x == 0) {
        unsigned gen = g_bar_gen;
        __threadfence();
        int s = blockIdx.x & 3;
        unsigned my = atomicAdd(&g_bar_sub[s], 1u) + 1u;
        if ((my % (NBLOCKS / 4)) == 0u) {
            unsigned r = atomicAdd(&g_bar_root, 1u) + 1u;
            if ((r & 3u) == 0u) { __threadfence(); g_bar_gen = gen + 1u; }
        }
        while (g_bar_gen == gen) __nanosleep(20);
        __threadfence();
    }
    __syncthreads();
}

// release/acquire helpers (gpu scope)
__device__ __forceinline__ unsigned ld_acq32(const unsigned* p) {
    unsigned v;
    asm volatile("ld.global.acquire.gpu.b32 %0, [%1];" : "=r"(v) : "l"(p) : "memory");
    return v;
}
__device__ __forceinline__ void st_rel32(unsigned* p, unsigned v) {
    asm volatile("st.global.release.gpu.b32 [%0], %1;" :: "l"(p), "r"(v) : "memory");
}
__device__ __forceinline__ unsigned long long ld_acq64(const unsigned long long* p) {
    unsigned long long v;
    asm volatile("ld.global.acquire.gpu.b64 %0, [%1];" : "=l"(v) : "l"(p) : "memory");
    return v;
}
__device__ __forceinline__ void st_rel64(unsigned long long* p, unsigned long long v) {
    asm volatile("st.global.release.gpu.b64 [%0], %1;" :: "l"(p), "l"(v) : "memory");
}

// Replicate XLA's acos lowering: acos(x)=2*atan2(sqrt(1-x*x),1+x), all f32 RN.
__device__ __forceinline__ float err_key(float w) {
    float x = fminf(fabsf(w), 1.0f);
    float t = __fsub_rn(1.0f, __fmul_rn(x, x));
    float s = __fsqrt_rn(t);
    float a = atan2f(s, __fadd_rn(1.0f, x));
    float acosv = __fmul_rn(2.0f, a);
    float deg   = __fmul_rn(acosv, 57.29577951308232f);
    return __fmul_rn(2.0f, deg);
}

struct Smem {
    int      s_u[CHUNK_CAP];
    unsigned s_winl[CHUNK_CAP];
    unsigned s_winr[CHUNK_CAP];
    int      s_off[CHUNK_CAP];
    int      s_wsum[NWB];
    int      s_woff[NWB];
    int      s_total, s_before, s_gtot, s_start;
    unsigned long long s_ctrl;
};

// Process one BFS level. Exact reference order: node v claimed by min key
// (queue_pos<<5 | rank); next-level queue = ascending winner key.
// big=true: all blocks (chunked, slotA tag barrier + per-level count gather).
// big=false: block 0 alone (__syncthreads only).
__device__ __forceinline__ int process_level(
    Smem& sm, const float4* __restrict__ ea4, float* __restrict__ out, int base,
    int lev, int beg, int end, int start, bool big)
{
    const int tid = threadIdx.x, lane = tid & 31, wid = tid >> 5, bid = blockIdx.x;
    const unsigned FULL = 0xffffffffu;
    const int len = end - beg;
    int cbeg, clen;
    if (big) {
        int chunk = (len + NBLOCKS - 1) / NBLOCKS;         // <= CHUNK_CAP
        cbeg = beg + bid * chunk;
        int cend = cbeg + chunk; if (cend > end) cend = end;
        clen = cend - cbeg; if (clen < 0) clen = 0;
    } else { cbeg = beg; clen = len; }
    const unsigned tag = (unsigned)(lev + 1);

    // acquire-spin queue entries (overlaps stragglers' Phase C of prior level)
    for (int i = tid; i < clen; i += NTHREADS) {
        unsigned qv;
        for (;;) {
            qv = ld_acq32(&g_queue[cbeg + i]);
            if ((qv >> 16) == tag) break;
            __nanosleep(20);
        }
        sm.s_u[i] = (int)(qv & 0xffffu);
    }
    __syncthreads();

    // Phase A: claims
    for (int ei = wid; ei < clen; ei += NWB) {
        unsigned pk = g_packed[(sm.s_u[ei] << 5) + lane];
        atomicMin(&g_claim[pk >> 5], (((unsigned)(cbeg + ei)) << 5) | (pk & 31u));
    }
    __syncthreads();
    if (big) {
        if (tid == 0) st_rel32(&g_slotA[bid], tag);
        if (wid == 0)
            for (int j = lane; j < NBLOCKS; j += 32)
                while (ld_acq32(&g_slotA[j]) < tag) __nanosleep(20);
        __syncthreads();
    }

    // Phase B: pipelined — issue all independent claim loads first, then ballots
    unsigned cl_arr[MAX_ITERS];
    #pragma unroll
    for (int it = 0; it < MAX_ITERS; it++) {
        int ei = wid + it * NWB;
        if (ei < clen) {
            unsigned pk = g_packed[(sm.s_u[ei] << 5) + lane];   // L1 hit
            cl_arr[it] = __ldcg(&g_claim[pk >> 5]);
        }
    }
    #pragma unroll
    for (int it = 0; it < MAX_ITERS; it++) {
        int ei = wid + it * NWB;
        if (ei < clen) {
            unsigned pk = g_packed[(sm.s_u[ei] << 5) + lane];   // L1 hit
            int v = (int)(pk >> 5); unsigned rk = pk & 31u;
            bool win = (v != start) &&
                       (cl_arr[it] == ((((unsigned)(cbeg + ei)) << 5) | rk));
            unsigned lm = __ballot_sync(FULL, win);
            unsigned rm = win ? (1u << rk) : 0u;
            #pragma unroll
            for (int d = 16; d; d >>= 1) rm |= __shfl_xor_sync(FULL, rm, d);
            if (lane == 0) { sm.s_winl[ei] = lm; sm.s_winr[ei] = rm; }
        }
    }
    __syncthreads();

    // exclusive scan of winner counts over the chunk
    int c = (tid < clen) ? __popc(sm.s_winl[tid]) : 0;
    int x = c;
    #pragma unroll
    for (int d = 1; d < 32; d <<= 1) {
        int y = __shfl_up_sync(FULL, x, d);
        if (lane >= d) x += y;
    }
    if (lane == 31) sm.s_wsum[wid] = x;
    __syncthreads();
    if (wid == 0 && lane < NWB) {
        int w = sm.s_wsum[lane], xx = w;
        #pragma unroll
        for (int d = 1; d < NWB; d <<= 1) {
            int y = __shfl_up_sync(0x0000ffffu, xx, d);
            if (lane >= d) xx += y;
        }
        sm.s_woff[lane] = xx - w;
        if (lane == NWB - 1) sm.s_total = xx;
    }
    __syncthreads();
    if (tid < clen) sm.s_off[tid] = x - c + sm.s_woff[wid];
    __syncthreads();

    int blkoff, gtot;
    if (big) {
        if (tid == 0)
            st_rel64(&g_cnt[lev][bid],
                     (((unsigned long long)tag) << 32) | (unsigned)sm.s_total);
        if (wid == 0) {
            // pipelined gather: poll all my slots per pass (<=4 with 112/32)
            int accb = 0, acct = 0;
            unsigned need = 0u;
            int nslots = 0;
            int js[4];
            for (int j = lane; j < NBLOCKS; j += 32) { js[nslots] = j; need |= 1u << nslots; nslots++; }
            unsigned long long vals[4];
            while (need) {
                unsigned long long tmp[4];
                #pragma unroll
                for (int k = 0; k < 4; k++)
                    if ((need >> k) & 1u) tmp[k] = ld_acq64(&g_cnt[lev][js[k]]);
                #pragma unroll
                for (int k = 0; k < 4; k++)
                    if (((need >> k) & 1u) && (unsigned)(tmp[k] >> 32) == tag) {
                        vals[k] = tmp[k];
                        need &= ~(1u << k);
                    }
                if (need) __nanosleep(20);
            }
            #pragma unroll
            for (int k = 0; k < 4; k++)
                if (k < nslots) {
                    int cc = (int)(vals[k] & 0xffffffffu);
                    acct += cc; if (js[k] < bid) accb += cc;
                }
            #pragma unroll
            for (int d = 16; d; d >>= 1) {
                accb += __shfl_xor_sync(FULL, accb, d);
                acct += __shfl_xor_sync(FULL, acct, d);
            }
            if (lane == 0) { sm.s_before = accb; sm.s_gtot = acct; }
        }
        __syncthreads();
        blkoff = end + sm.s_before;
        gtot   = sm.s_gtot;
    } else {
        blkoff = end;
        gtot   = sm.s_total;
    }

    // Phase C: quat at claim time; release-tagged queue write (no barrier after)
    for (int ei = wid; ei < clen; ei += NWB) {
        unsigned lm = sm.s_winl[ei];
        if (!lm) continue;
        if ((lm >> lane) & 1u) {
            int u = sm.s_u[ei];
            int e = (u << 5) + lane;
            unsigned pk = g_packed[e];
            int v = (int)(pk >> 5); unsigned rk = pk & 31u;
            unsigned rm = sm.s_winr[ei];
            int pos = blkoff + sm.s_off[ei] + __popc(rm & ((1u << rk) - 1u));
            float4 q  = ea4[e];
            float4 uq = __ldcg(&g_nq[u]);
            // qmul(inv(q), qu):  inv(q) = (w, -x, -y, -z)
            float w1 = q.x, x1 = -q.y, y1 = -q.z, z1 = -q.w;
            float4 r;
            r.x = w1*uq.x - x1*uq.y - y1*uq.z - z1*uq.w;
            r.y = w1*uq.y + x1*uq.x + y1*uq.w - z1*uq.z;
            r.z = w1*uq.z - x1*uq.w + y1*uq.x + z1*uq.y;
            r.w = w1*uq.w + x1*uq.z - y1*uq.y + z1*uq.x;
            __stcg(&g_nq[v], r);
            __stcg(&out[base + 4*v + 0], r.x);
            __stcg(&out[base + 4*v + 1], r.y);
            __stcg(&out[base + 4*v + 2], r.z);
            __stcg(&out[base + 4*v + 3], r.w);
            st_rel32(&g_queue[pos], ((tag + 1u) << 16) | (unsigned)v);
        }
    }
    __syncthreads();   // s_* reuse safety for next level
    return gtot;
}

__global__ __launch_bounds__(NTHREADS, 1)
void spt_kernel(const float* __restrict__ edge_attr,
                const int*   __restrict__ edge_index,
                const int*   __restrict__ start_ptr,
                float* __restrict__ out, int N, int E, int base) {
    __shared__ Smem sm;
    const int tid = threadIdx.x, lane = tid & 31, wid = tid >> 5, bid = blockIdx.x;
    const unsigned FULL = 0xffffffffu;

    if (tid == 0) {
        int s = start_ptr ? __ldcg(start_ptr) : 0;
        if (s < 0 || s >= N) s = 0;
        sm.s_start = s;
    }
    __syncthreads();
    const int start = sm.s_start;

    // ---- per-run resets (pre-barrier) ----
    if (tid == 0) {
        g_slotA[bid] = 0u;
        if (bid == 0) {
            g_ctrl = 0ULL;
            g_nq[start] = make_float4(1.f, 0.f, 0.f, 0.f);
            for (int i = 0; i < base; i++) out[i] = (float)start;
        }
    }
    for (int l = tid; l < MAX_LEV + 2; l += NTHREADS) g_cnt[l][bid] = 0ULL;

    for (int i = bid * NTHREADS + tid; i < N; i += NBLOCKS * NTHREADS) {
        g_claim[i] = 0xffffffffu;
        g_queue[i] = (i == 0) ? ((1u << 16) | (unsigned)start) : 0u;
        out[base + 4*i + 0] = 1.f;
        out[base + 4*i + 1] = 0.f;
        out[base + 4*i + 2] = 0.f;
        out[base + 4*i + 3] = 0.f;
    }

    // ---- rank phase: stable rank of each edge within its node ----
    for (int node = bid * NWB + wid; node < N; node += NBLOCKS * NWB) {
        int e = (node << 5) + lane;
        int v = edge_index[E + e];             // dst row of edge_index [2,E]
        float err = err_key(edge_attr[4 * e]); // component 0 = w
        unsigned kb = __float_as_uint(err);    // err>=0: bits order-preserving
        int rk = 0;
        #pragma unroll
        for (int j = 0; j < 32; j++) {
            unsigned kj = __shfl_sync(FULL, kb, j);
            rk += (kj < kb) || (kj == kb && j < lane);
        }
        g_packed[e] = (((unsigned)v) << 5) | (unsigned)rk;
    }

    grid_barrier();

    // ---- level-synchronous BFS (R7 sync topology) ----
    const float4* ea4 = reinterpret_cast<const float4*>(edge_attr);
    int lev = 0, beg = 0, end = 1;
    unsigned long long last_ctrl = 0ULL;
    bool prev_big = false;

    while (true) {
        int len = end - beg;
        if (len <= 0 || lev >= MAX_LEV) {
            if (bid == 0 && tid == 0)
                st_rel64(&g_ctrl, (1ULL << 63) |
                                  (((unsigned long long)(lev + 1)) << 32));
            return;
        }
        bool fast = (len <= FAST_MAX);
        if (fast && bid != 0) {
            // sleep until block 0 publishes the next big level (or DONE)
            if (tid == 0) {
                unsigned long long cw;
                for (;;) {
                    cw = ld_acq64(&g_ctrl);
                    if (cw != last_ctrl) break;
                    __nanosleep(60);
                }
                sm.s_ctrl = cw;
            }
            __syncthreads();
            unsigned long long cw = sm.s_ctrl;
            last_ctrl = cw;
            if (cw >> 63) return;
            lev = (int)((cw >> 32) & 0xffffu) - 1;
            beg = (int)((cw >> 16) & 0xffffu);
            end = (int)(cw & 0xffffu);
            int gtot = process_level(sm, ea4, out, base, lev, beg, end, start, true);
            prev_big = true;
            beg = end; end += gtot; lev++;
            continue;
        }
        if (!fast && !prev_big && bid == 0 && tid == 0)
            st_rel64(&g_ctrl, (((unsigned long long)(lev + 1)) << 32) |
                              (((unsigned long long)beg) << 16) | (unsigned)end);
        int gtot = process_level(sm, ea4, out, base, lev, beg, end, start, !fast);
        prev_big = !fast;
        beg = end; end += gtot; lev++;
    }
}

extern "C" void kernel_launch(void* const* d_in, const int* in_sizes, int n_in,
                              void* d_out, int out_size) {
    const float* edge_attr  = (const float*)d_in[0];
    const int*   edge_index = (const int*)d_in[1];
    const int*   start_ptr  = (n_in >= 3) ? (const int*)d_in[2] : nullptr;
    float* out = (float*)d_out;

    int E = in_sizes[0] / 4;     // edge_attr is [E,4]
    int N = E / DEG;
    if (N > N_MAX) N = N_MAX;
    int base = out_size - N * 4;
    if (base < 0) base = 0;

    spt_kernel<<<NBLOCKS, NTHREADS>>>(edge_attr, edge_index, start_ptr, out, N, E, base);
}